// round 4
// baseline (speedup 1.0000x reference)
#include <cuda_runtime.h>

#define NN 100000

// ---- scratch (static __device__ globals; no allocation) ----
__device__ int    g_deg[NN];       // zero-init; reset to 0 by k_node_prep each run
__device__ float4 g_R[NN];         // {S.x, S.y, S.z, dinv}  (layer-1 accum + dinv payload)
__device__ float4 g_Q[NN];         // {sx.x, sx.y, sx.z, w-accum}
__device__ float  g_sum16[16];     // final 16-dim reduction (layer2 agg sum)

// ---------------------------------------------------------------------------
// degree histogram over dst (deg EXCLUDES self-loop; added in node_prep)
__global__ void k_hist(const int* __restrict__ dst, int E) {
    int i      = blockIdx.x * blockDim.x + threadIdx.x;
    int stride = gridDim.x * blockDim.x;
    for (int e = i; e < E; e += stride) {
        atomicAdd(&g_deg[dst[e]], 1);
    }
}

// per-node: dinv = rsqrt(deg+1); Q = {dinv*x, dinv}; R = {0,0,0,dinv};
// resets deg for next graph replay; zeroes sum16 (block 0).
__global__ void k_node_prep(const float* __restrict__ x) {
    int v = blockIdx.x * blockDim.x + threadIdx.x;
    if (blockIdx.x == 0 && threadIdx.x < 16) g_sum16[threadIdx.x] = 0.f;
    if (v >= NN) return;
    float d = rsqrtf((float)(g_deg[v] + 1));   // +1 = self-loop
    g_deg[v] = 0;                              // reset for next replay
    g_R[v] = make_float4(0.f, 0.f, 0.f, d);
    g_Q[v] = make_float4(d * x[3 * v + 0], d * x[3 * v + 1], d * x[3 * v + 2], d);
}

// fused edge pass, 3 random lane-accesses per edge:
//   1) gather Q[s]           -> sx
//   2) atom.v4 R[d] += (sx,0) -> returns old, old.w = dinv[d]   (scatter + gather in one)
//   3) red Q[s].w += dinv[d]                                      (layer-2 weight)
__global__ void k_scatter(const int* __restrict__ src,
                          const int* __restrict__ dst, int E) {
    int i      = blockIdx.x * blockDim.x + threadIdx.x;
    int stride = gridDim.x * blockDim.x;
    for (int e = i; e < E; e += stride) {
        int s = src[e];
        int d = dst[e];
        float4 q = g_Q[s];                     // .xyz immutable after node_prep
        float o0, o1, o2, o3;
        asm volatile("atom.global.add.v4.f32 {%0,%1,%2,%3}, [%4], {%5,%6,%7,%8};"
                     : "=f"(o0), "=f"(o1), "=f"(o2), "=f"(o3)
                     : "l"(&g_R[d]), "f"(q.x), "f"(q.y), "f"(q.z), "f"(0.0f)
                     : "memory");
        // o3 == dinv[d] (w-lane addend is 0, value set once in node_prep)
        asm volatile("red.global.add.f32 [%0], %1;"
                     :: "l"(&((float*)&g_Q[s])[3]), "f"(o3)
                     : "memory");
    }
}

// block-wide reduce of 16 per-thread floats into g_sum16 (256 threads fixed)
__device__ __forceinline__ void block_reduce_add16(float* acc) {
    #pragma unroll
    for (int j = 0; j < 16; j++) {
        #pragma unroll
        for (int o = 16; o > 0; o >>= 1)
            acc[j] += __shfl_down_sync(0xffffffffu, acc[j], o);
    }
    __shared__ float sm[8][16];
    int lane = threadIdx.x & 31, w = threadIdx.x >> 5;
    if (lane == 0) {
        #pragma unroll
        for (int j = 0; j < 16; j++) sm[w][j] = acc[j];
    }
    __syncthreads();
    if (threadIdx.x < 16) {
        float s = 0.f;
        #pragma unroll
        for (int ww = 0; ww < 8; ww++) s += sm[ww][threadIdx.x];
        atomicAdd(&g_sum16[threadIdx.x], s);
    }
}

// layer-1 per-node + layer-2 accumulation:
//   a = dinv*(S + sx);  h1 = relu(a @ W1 + b1);  sum16 += (w * dinv) * h1
__global__ void k_layer1(const float* __restrict__ W1, const float* __restrict__ b1) {
    int v = blockIdx.x * blockDim.x + threadIdx.x;
    float acc[16];
    #pragma unroll
    for (int j = 0; j < 16; j++) acc[j] = 0.f;

    if (v < NN) {
        float4 R = g_R[v];           // S.xyz, dinv
        float4 Q = g_Q[v];           // sx.xyz, w
        float  d  = R.w;
        float  wv = Q.w * d;         // w[v] * dinv[v]
        float a0 = d * (R.x + Q.x);
        float a1 = d * (R.y + Q.y);
        float a2 = d * (R.z + Q.z);
        #pragma unroll
        for (int j = 0; j < 16; j++) {
            float h = __ldg(&b1[j])
                    + a0 * __ldg(&W1[j])
                    + a1 * __ldg(&W1[16 + j])
                    + a2 * __ldg(&W1[32 + j]);
            h = fmaxf(h, 0.f);
            acc[j] = wv * h;
        }
    }
    block_reduce_add16(acc);
}

// final: out[j] = (sum16/N) @ W2 + b2
__global__ void k_final(const float* __restrict__ W2, const float* __restrict__ b2,
                        float* __restrict__ out) {
    int j = threadIdx.x;
    if (j >= 32) return;
    float s = __ldg(&b2[j]);
    const float inv_n = 1.0f / (float)NN;
    #pragma unroll
    for (int k = 0; k < 16; k++)
        s += (g_sum16[k] * inv_n) * __ldg(&W2[k * 32 + j]);
    out[j] = s;
}

// ---------------------------------------------------------------------------
extern "C" void kernel_launch(void* const* d_in, const int* in_sizes, int n_in,
                              void* d_out, int out_size) {
    const float* x   = (const float*)d_in[0];
    const int*   ei  = (const int*)d_in[1];
    const float* W1  = (const float*)d_in[2];
    const float* b1  = (const float*)d_in[3];
    const float* W2  = (const float*)d_in[4];
    const float* b2  = (const float*)d_in[5];
    float*       out = (float*)d_out;

    int E = in_sizes[1] / 2;
    const int* src = ei;
    const int* dst = ei + E;

    int nb_nodes = (NN + 255) / 256;
    int nb_edges = (E + 255) / 256;
    if (nb_edges > 9600) nb_edges = 9600;   // grid-stride

    k_hist<<<nb_edges, 256>>>(dst, E);
    k_node_prep<<<nb_nodes, 256>>>(x);
    k_scatter<<<nb_edges, 256>>>(src, dst, E);
    k_layer1<<<nb_nodes, 256>>>(W1, b1);
    k_final<<<1, 32>>>(W2, b2, out);
}

// round 5
// speedup vs baseline: 1.0057x; 1.0057x over previous
#include <cuda_runtime.h>

#define NN 100000
#define L1_BLOCKS 391   // ceil(NN/256)

// ---- scratch (static __device__ globals; no allocation) ----
__device__ int    g_deg[NN];            // zero at load; node_prep resets to 0 each run
__device__ float  g_dinv[NN];
__device__ float4 g_S[NN];              // layer-1 accumulator (w lane = unused garbage)
__device__ float4 g_Q[NN];              // {sx.xyz, w-accum}
__device__ float  g_part[L1_BLOCKS][16];// per-block layer-2 partials

// ---------------------------------------------------------------------------
// degree histogram over dst (self-loop added in node_prep)
__global__ void k_hist(const int* __restrict__ dst, int E) {
    int i      = blockIdx.x * blockDim.x + threadIdx.x;
    int stride = gridDim.x * blockDim.x;
    for (int e = i; e < E; e += stride) {
        atomicAdd(&g_deg[dst[e]], 1);
    }
}

// per-node: dinv = rsqrt(deg+1); Q = {dinv*x, dinv}; S = 0; reset deg for replay
__global__ void k_node_prep(const float* __restrict__ x) {
    int v = blockIdx.x * blockDim.x + threadIdx.x;
    if (v >= NN) return;
    float d = rsqrtf((float)(g_deg[v] + 1));
    g_deg[v]  = 0;                       // deterministic across graph replays
    g_dinv[v] = d;
    g_S[v] = make_float4(0.f, 0.f, 0.f, 0.f);
    g_Q[v] = make_float4(d * x[3 * v + 0], d * x[3 * v + 1], d * x[3 * v + 2], d);
}

// fused edge pass, 4 divergent lanes per edge:
//   gather Q[s] (16B), gather dinv[d] (4B),
//   red.v4 S[d] += Q[s]  (w lane accumulates junk, unused),
//   red Q[s].w += dinv[d]  (layer-2 source weight)
__global__ void k_scatter(const int* __restrict__ src,
                          const int* __restrict__ dst, int E) {
    int i      = blockIdx.x * blockDim.x + threadIdx.x;
    int stride = gridDim.x * blockDim.x;
    for (int e = i; e < E; e += stride) {
        int s = src[e];
        int d = dst[e];
        float4 q  = g_Q[s];              // xyz immutable during this pass
        float  dd = g_dinv[d];
        asm volatile("red.global.add.v4.f32 [%0], {%1,%2,%3,%4};"
                     :: "l"(&g_S[d]), "f"(q.x), "f"(q.y), "f"(q.z), "f"(q.w)
                     : "memory");
        asm volatile("red.global.add.f32 [%0], %1;"
                     :: "l"(&((float*)&g_Q[s])[3]), "f"(dd)
                     : "memory");
    }
}

// layer-1 per-node + layer-2 accumulation, per-block partials (NO global atomics):
//   a = dinv*(S + sx);  h1 = relu(a @ W1 + b1);  part[block] += (w*dinv)*h1
__global__ void k_layer1(const float* __restrict__ W1, const float* __restrict__ b1) {
    int v = blockIdx.x * blockDim.x + threadIdx.x;
    float acc[16];
    #pragma unroll
    for (int j = 0; j < 16; j++) acc[j] = 0.f;

    if (v < NN) {
        float4 S = g_S[v];
        float4 Q = g_Q[v];
        float  d = g_dinv[v];
        float  wv = Q.w * d;
        float a0 = d * (S.x + Q.x);
        float a1 = d * (S.y + Q.y);
        float a2 = d * (S.z + Q.z);
        #pragma unroll
        for (int j = 0; j < 16; j++) {
            float h = __ldg(&b1[j])
                    + a0 * __ldg(&W1[j])
                    + a1 * __ldg(&W1[16 + j])
                    + a2 * __ldg(&W1[32 + j]);
            acc[j] = wv * fmaxf(h, 0.f);
        }
    }

    // warp reduce 16 floats
    #pragma unroll
    for (int j = 0; j < 16; j++) {
        #pragma unroll
        for (int o = 16; o > 0; o >>= 1)
            acc[j] += __shfl_down_sync(0xffffffffu, acc[j], o);
    }
    __shared__ float sm[8][16];
    int lane = threadIdx.x & 31, w = threadIdx.x >> 5;
    if (lane == 0) {
        #pragma unroll
        for (int j = 0; j < 16; j++) sm[w][j] = acc[j];
    }
    __syncthreads();
    if (threadIdx.x < 16) {
        float s = 0.f;
        #pragma unroll
        for (int ww = 0; ww < 8; ww++) s += sm[ww][threadIdx.x];
        g_part[blockIdx.x][threadIdx.x] = s;     // plain store
    }
}

// reduce partials; out[j] = (sum16/N) @ W2 + b2
__global__ void k_final(const float* __restrict__ W2, const float* __restrict__ b2,
                        float* __restrict__ out) {
    __shared__ float red[16][16];
    __shared__ float sum16[16];
    int tid = threadIdx.x;          // 256 threads
    int j = tid & 15;               // column
    int g = tid >> 4;               // group 0..15
    float s = 0.f;
    for (int b = g; b < L1_BLOCKS; b += 16)
        s += g_part[b][j];
    red[g][j] = s;
    __syncthreads();
    if (tid < 16) {
        float t = 0.f;
        #pragma unroll
        for (int gg = 0; gg < 16; gg++) t += red[gg][tid];
        sum16[tid] = t * (1.0f / (float)NN);
    }
    __syncthreads();
    if (tid < 32) {
        float o = __ldg(&b2[tid]);
        #pragma unroll
        for (int k = 0; k < 16; k++)
            o += sum16[k] * __ldg(&W2[k * 32 + tid]);
        out[tid] = o;
    }
}

// ---------------------------------------------------------------------------
extern "C" void kernel_launch(void* const* d_in, const int* in_sizes, int n_in,
                              void* d_out, int out_size) {
    const float* x   = (const float*)d_in[0];
    const int*   ei  = (const int*)d_in[1];
    const float* W1  = (const float*)d_in[2];
    const float* b1  = (const float*)d_in[3];
    const float* W2  = (const float*)d_in[4];
    const float* b2  = (const float*)d_in[5];
    float*       out = (float*)d_out;

    int E = in_sizes[1] / 2;
    const int* src = ei;
    const int* dst = ei + E;

    int nb_edges = (E + 255) / 256;
    if (nb_edges > 9600) nb_edges = 9600;   // grid-stride

    k_hist<<<nb_edges, 256>>>(dst, E);
    k_node_prep<<<L1_BLOCKS, 256>>>(x);
    k_scatter<<<nb_edges, 256>>>(src, dst, E);
    k_layer1<<<L1_BLOCKS, 256>>>(W1, b1);
    k_final<<<1, 256>>>(W2, b2, out);
}